// round 14
// baseline (speedup 1.0000x reference)
#include <cuda_runtime.h>
#include <cuda_fp16.h>

// Problem: GridSamplePScan  B=1, L=16, C=8, H=128, W=128
// out[t,c,h,w] = sum_{k<=t} bilinear(images[k,c], base(h,w) + cum[t]-cum[k])
// x wrapped periodically, zero-padding taps.
//
// R9: row-duplicated NHWC fp16 scratch dup[l][y][x][r][c] = img[l][y+r][x][c].
//     A point's entire 2x2 bilinear footprint = 64 contiguous bytes; 4 lanes
//     per point (sx=side, r=row) -> ONE LDG.128 serves 8 points completely.
//     1.25 L1 wavefronts/point vs 2.25 in R7.

#define L_ 16
#define C_ 8
#define H_ 128
#define W_ 128
#define HW_ (H_ * W_)

// row-duplicated NHWC fp16 scratch: [L, H, W, 2, C] halves = 8 MB
__device__ __half g_imgD[L_ * HW_ * 2 * C_];
// cumulative flows: [L, HW] float2 = 2 MB
__device__ float2 g_cum[L_ * HW_];

// ---------------------------------------------------------------------------
// Kernel 1: build dup layout. Thread (k, y, x) reads img row y (8 ch),
// writes slot (y, r=0) and slot (y-1, r=1); top block r=1 gets clamp fill.
// ---------------------------------------------------------------------------
__global__ __launch_bounds__(256) void build_dup_kernel(const float* __restrict__ images) {
    int idx = blockIdx.x * blockDim.x + threadIdx.x;  // over L*H*W
    if (idx >= L_ * HW_) return;
    int k = idx >> 14;
    int hw = idx & (HW_ - 1);
    int y = hw >> 7;

    const float* src = images + (size_t)k * C_ * HW_ + hw;
    __half2 h0 = __floats2half2_rn(src[0 * HW_], src[1 * HW_]);
    __half2 h1 = __floats2half2_rn(src[2 * HW_], src[3 * HW_]);
    __half2 h2 = __floats2half2_rn(src[4 * HW_], src[5 * HW_]);
    __half2 h3 = __floats2half2_rn(src[6 * HW_], src[7 * HW_]);

    uint4 pack;
    pack.x = *reinterpret_cast<unsigned int*>(&h0);
    pack.y = *reinterpret_cast<unsigned int*>(&h1);
    pack.z = *reinterpret_cast<unsigned int*>(&h2);
    pack.w = *reinterpret_cast<unsigned int*>(&h3);

    // r=0 slot of block y
    *reinterpret_cast<uint4*>(g_imgD + ((size_t)idx * 2 + 0) * C_) = pack;
    // r=1 slot of block y-1 (this row is that block's second row)
    if (y > 0)
        *reinterpret_cast<uint4*>(g_imgD + ((size_t)(idx - W_) * 2 + 1) * C_) = pack;
    // top block's r=1 slot: clamp fill (finite; weight is always 0 there)
    if (y == H_ - 1)
        *reinterpret_cast<uint4*>(g_imgD + ((size_t)idx * 2 + 1) * C_) = pack;
}

// ---------------------------------------------------------------------------
// Kernel 2: cumsum of flows over t.  flows [L,2,H,W] -> g_cum [L,HW] float2
// ---------------------------------------------------------------------------
__global__ __launch_bounds__(256) void cumsum_flows_kernel(const float* __restrict__ flows) {
    int hw = blockIdx.x * blockDim.x + threadIdx.x;
    if (hw >= HW_) return;
    float ax = 0.0f, ay = 0.0f;
#pragma unroll
    for (int t = 0; t < L_; ++t) {
        ax += flows[(size_t)(t * 2 + 0) * HW_ + hw];
        ay += flows[(size_t)(t * 2 + 1) * HW_ + hw];
        g_cum[t * HW_ + hw] = make_float2(ax, ay);
    }
}

// ---------------------------------------------------------------------------
// Kernel 3: quad-lane bilinear gather + triangular accumulation.
// Block = 512 threads: quad (4 lanes) per pixel; lane s: sx=s>>1 (x side),
// r=s&1 (row). One LDG.128 per (k, 8 points). 2-level shfl merge at end.
// ---------------------------------------------------------------------------
__device__ __forceinline__ void accum_tap(const uint4 p, const float wgt,
                                          float& a0, float& a1, float& a2, float& a3,
                                          float& a4, float& a5, float& a6, float& a7) {
    __half2 h0 = *reinterpret_cast<const __half2*>(&p.x);
    __half2 h1 = *reinterpret_cast<const __half2*>(&p.y);
    __half2 h2 = *reinterpret_cast<const __half2*>(&p.z);
    __half2 h3 = *reinterpret_cast<const __half2*>(&p.w);
    float2 f0 = __half22float2(h0);
    float2 f1 = __half22float2(h1);
    float2 f2 = __half22float2(h2);
    float2 f3 = __half22float2(h3);
    a0 = fmaf(wgt, f0.x, a0);
    a1 = fmaf(wgt, f0.y, a1);
    a2 = fmaf(wgt, f1.x, a2);
    a3 = fmaf(wgt, f1.y, a3);
    a4 = fmaf(wgt, f2.x, a4);
    a5 = fmaf(wgt, f2.y, a5);
    a6 = fmaf(wgt, f3.x, a6);
    a7 = fmaf(wgt, f3.y, a7);
}

__global__ __launch_bounds__(512) void pscan_sample_kernel(float* __restrict__ out) {
    const int tid = threadIdx.x;              // 0..511
    const int w   = tid >> 2;                 // pixel column 0..127
    const int s   = tid & 3;                  // tap slot within quad
    const int sx  = s >> 1;                   // x side: 0 -> x0, 1 -> x1
    const int r   = s & 1;                    // row within dup block
    const int h = blockIdx.x;                 // 0..127
    const int t = (L_ - 1) - blockIdx.y;      // long blocks first
    const int hw = h * W_ + w;

    const float bx = (2.0f * (float)w + 1.0f) * (1.0f / (float)W_) - 1.0f;
    const float by = (2.0f * (float)h + 1.0f) * (1.0f / (float)H_) - 1.0f;

    const float2 ct = g_cum[t * HW_ + hw];

    float a0 = 0.f, a1 = 0.f, a2 = 0.f, a3 = 0.f;
    float a4 = 0.f, a5 = 0.f, a6 = 0.f, a7 = 0.f;

    const char* imgk = reinterpret_cast<const char*>(g_imgD);  // advance by 512KB per k
#pragma unroll 2
    for (int k = 0; k <= t; ++k) {
        const float2 ck = g_cum[k * HW_ + hw];

        float gx = bx + (ct.x - ck.x);
        float gy = by + (ct.y - ck.y);

        // periodic wrap in x: Python remainder(gx+1, 2) - 1 via floor-mod
        float xp = gx + 1.0f;
        gx = xp - 2.0f * floorf(xp * 0.5f) - 1.0f;

        float ix = (gx + 1.0f) * ((float)W_ * 0.5f) - 0.5f;
        float iy = (gy + 1.0f) * ((float)H_ * 0.5f) - 0.5f;

        float x0f = floorf(ix);
        float y0f = floorf(iy);
        float wx = ix - x0f;
        float wy = iy - y0f;

        int x0 = (int)x0f;
        int y0 = (int)y0f;
        int y1 = y0 + 1;

        // this lane's x tap
        int xs = x0 + sx;
        float wxs = sx ? wx : (1.0f - wx);
        float vx = (xs >= 0 && xs < W_) ? 1.0f : 0.0f;
        int cx = min(max(xs, 0), W_ - 1);

        // this lane's row within dup block b
        int b = min(max(y0, 0), H_ - 1);
        int row = b + r;
        float wys = (row == y0 && row < H_) ? (1.0f - wy)
                  : ((row == y1 && row < H_) ? wy : 0.0f);

        float wgt = wxs * vx * wys;

        // dup slot address: ((b*W + cx)*2 + r) * 16 bytes
        const uint4 p = *reinterpret_cast<const uint4*>(
            imgk + (((size_t)(b * W_ + cx) << 1) + r) * (C_ * sizeof(__half)));

        accum_tap(p, wgt, a0, a1, a2, a3, a4, a5, a6, a7);

        imgk += (size_t)HW_ * 2 * C_ * sizeof(__half);
    }

    // merge the quad: xor 1 (row pairs), xor 2 (x sides)
    a0 += __shfl_xor_sync(0xFFFFFFFFu, a0, 1);
    a1 += __shfl_xor_sync(0xFFFFFFFFu, a1, 1);
    a2 += __shfl_xor_sync(0xFFFFFFFFu, a2, 1);
    a3 += __shfl_xor_sync(0xFFFFFFFFu, a3, 1);
    a4 += __shfl_xor_sync(0xFFFFFFFFu, a4, 1);
    a5 += __shfl_xor_sync(0xFFFFFFFFu, a5, 1);
    a6 += __shfl_xor_sync(0xFFFFFFFFu, a6, 1);
    a7 += __shfl_xor_sync(0xFFFFFFFFu, a7, 1);

    a0 += __shfl_xor_sync(0xFFFFFFFFu, a0, 2);
    a1 += __shfl_xor_sync(0xFFFFFFFFu, a1, 2);
    a2 += __shfl_xor_sync(0xFFFFFFFFu, a2, 2);
    a3 += __shfl_xor_sync(0xFFFFFFFFu, a3, 2);
    a4 += __shfl_xor_sync(0xFFFFFFFFu, a4, 2);
    a5 += __shfl_xor_sync(0xFFFFFFFFu, a5, 2);
    a6 += __shfl_xor_sync(0xFFFFFFFFu, a6, 2);
    a7 += __shfl_xor_sync(0xFFFFFFFFu, a7, 2);

    if (s == 0) {
        float* o = out + (size_t)t * C_ * HW_ + hw;
        o[0 * HW_] = a0;
        o[1 * HW_] = a1;
        o[2 * HW_] = a2;
        o[3 * HW_] = a3;
        o[4 * HW_] = a4;
        o[5 * HW_] = a5;
        o[6 * HW_] = a6;
        o[7 * HW_] = a7;
    }
}

// ---------------------------------------------------------------------------
extern "C" void kernel_launch(void* const* d_in, const int* in_sizes, int n_in,
                              void* d_out, int out_size) {
    const float* flows  = (const float*)d_in[0];   // [1,16,2,128,128]
    const float* images = (const float*)d_in[1];   // [1,16,8,128,128]
    float* out = (float*)d_out;                    // [1,16,8,128,128]

    (void)in_sizes; (void)n_in; (void)out_size;

    {
        int total = L_ * HW_;
        build_dup_kernel<<<(total + 255) / 256, 256>>>(images);
    }
    {
        cumsum_flows_kernel<<<(HW_ + 255) / 256, 256>>>(flows);
    }
    {
        dim3 grid(H_, L_);
        dim3 block(512);
        pscan_sample_kernel<<<grid, block>>>(out);
    }
}

// round 15
// speedup vs baseline: 1.0077x; 1.0077x over previous
#include <cuda_runtime.h>
#include <cuda_fp16.h>

// Problem: GridSamplePScan  B=1, L=16, C=8, H=128, W=128
// out[t,c,h,w] = sum_{k<=t} bilinear(images[k,c], base(h,w) + cum[t]-cum[k])
// x wrapped periodically, zero-padding taps.
//
// R9: row-duplicated NHWC fp16 scratch dup[l][y][x][r][c] = img[l][y+r][x][c].
//     A point's entire 2x2 bilinear footprint = 64 contiguous bytes; 4 lanes
//     per point (sx=side, r=row) -> ONE LDG.128 serves 8 points completely.
//     1.25 L1 wavefronts/point vs 2.25 in R7.

#define L_ 16
#define C_ 8
#define H_ 128
#define W_ 128
#define HW_ (H_ * W_)

// row-duplicated NHWC fp16 scratch: [L, H, W, 2, C] halves = 8 MB
__device__ __half g_imgD[L_ * HW_ * 2 * C_];
// cumulative flows: [L, HW] float2 = 2 MB
__device__ float2 g_cum[L_ * HW_];

// ---------------------------------------------------------------------------
// Kernel 1: build dup layout. Thread (k, y, x) reads img row y (8 ch),
// writes slot (y, r=0) and slot (y-1, r=1); top block r=1 gets clamp fill.
// ---------------------------------------------------------------------------
__global__ __launch_bounds__(256) void build_dup_kernel(const float* __restrict__ images) {
    int idx = blockIdx.x * blockDim.x + threadIdx.x;  // over L*H*W
    if (idx >= L_ * HW_) return;
    int k = idx >> 14;
    int hw = idx & (HW_ - 1);
    int y = hw >> 7;

    const float* src = images + (size_t)k * C_ * HW_ + hw;
    __half2 h0 = __floats2half2_rn(src[0 * HW_], src[1 * HW_]);
    __half2 h1 = __floats2half2_rn(src[2 * HW_], src[3 * HW_]);
    __half2 h2 = __floats2half2_rn(src[4 * HW_], src[5 * HW_]);
    __half2 h3 = __floats2half2_rn(src[6 * HW_], src[7 * HW_]);

    uint4 pack;
    pack.x = *reinterpret_cast<unsigned int*>(&h0);
    pack.y = *reinterpret_cast<unsigned int*>(&h1);
    pack.z = *reinterpret_cast<unsigned int*>(&h2);
    pack.w = *reinterpret_cast<unsigned int*>(&h3);

    // r=0 slot of block y
    *reinterpret_cast<uint4*>(g_imgD + ((size_t)idx * 2 + 0) * C_) = pack;
    // r=1 slot of block y-1 (this row is that block's second row)
    if (y > 0)
        *reinterpret_cast<uint4*>(g_imgD + ((size_t)(idx - W_) * 2 + 1) * C_) = pack;
    // top block's r=1 slot: clamp fill (finite; weight is always 0 there)
    if (y == H_ - 1)
        *reinterpret_cast<uint4*>(g_imgD + ((size_t)idx * 2 + 1) * C_) = pack;
}

// ---------------------------------------------------------------------------
// Kernel 2: cumsum of flows over t.  flows [L,2,H,W] -> g_cum [L,HW] float2
// ---------------------------------------------------------------------------
__global__ __launch_bounds__(256) void cumsum_flows_kernel(const float* __restrict__ flows) {
    int hw = blockIdx.x * blockDim.x + threadIdx.x;
    if (hw >= HW_) return;
    float ax = 0.0f, ay = 0.0f;
#pragma unroll
    for (int t = 0; t < L_; ++t) {
        ax += flows[(size_t)(t * 2 + 0) * HW_ + hw];
        ay += flows[(size_t)(t * 2 + 1) * HW_ + hw];
        g_cum[t * HW_ + hw] = make_float2(ax, ay);
    }
}

// ---------------------------------------------------------------------------
// Kernel 3: quad-lane bilinear gather + triangular accumulation.
// Block = 512 threads: quad (4 lanes) per pixel; lane s: sx=s>>1 (x side),
// r=s&1 (row). One LDG.128 per (k, 8 points). 2-level shfl merge at end.
// ---------------------------------------------------------------------------
__device__ __forceinline__ void accum_tap(const uint4 p, const float wgt,
                                          float& a0, float& a1, float& a2, float& a3,
                                          float& a4, float& a5, float& a6, float& a7) {
    __half2 h0 = *reinterpret_cast<const __half2*>(&p.x);
    __half2 h1 = *reinterpret_cast<const __half2*>(&p.y);
    __half2 h2 = *reinterpret_cast<const __half2*>(&p.z);
    __half2 h3 = *reinterpret_cast<const __half2*>(&p.w);
    float2 f0 = __half22float2(h0);
    float2 f1 = __half22float2(h1);
    float2 f2 = __half22float2(h2);
    float2 f3 = __half22float2(h3);
    a0 = fmaf(wgt, f0.x, a0);
    a1 = fmaf(wgt, f0.y, a1);
    a2 = fmaf(wgt, f1.x, a2);
    a3 = fmaf(wgt, f1.y, a3);
    a4 = fmaf(wgt, f2.x, a4);
    a5 = fmaf(wgt, f2.y, a5);
    a6 = fmaf(wgt, f3.x, a6);
    a7 = fmaf(wgt, f3.y, a7);
}

__global__ __launch_bounds__(512) void pscan_sample_kernel(float* __restrict__ out) {
    const int tid = threadIdx.x;              // 0..511
    const int w   = tid >> 2;                 // pixel column 0..127
    const int s   = tid & 3;                  // tap slot within quad
    const int sx  = s >> 1;                   // x side: 0 -> x0, 1 -> x1
    const int r   = s & 1;                    // row within dup block
    const int h = blockIdx.x;                 // 0..127
    const int t = (L_ - 1) - blockIdx.y;      // long blocks first
    const int hw = h * W_ + w;

    const float bx = (2.0f * (float)w + 1.0f) * (1.0f / (float)W_) - 1.0f;
    const float by = (2.0f * (float)h + 1.0f) * (1.0f / (float)H_) - 1.0f;

    const float2 ct = g_cum[t * HW_ + hw];

    float a0 = 0.f, a1 = 0.f, a2 = 0.f, a3 = 0.f;
    float a4 = 0.f, a5 = 0.f, a6 = 0.f, a7 = 0.f;

    const char* imgk = reinterpret_cast<const char*>(g_imgD);  // advance by 512KB per k
#pragma unroll 2
    for (int k = 0; k <= t; ++k) {
        const float2 ck = g_cum[k * HW_ + hw];

        float gx = bx + (ct.x - ck.x);
        float gy = by + (ct.y - ck.y);

        // periodic wrap in x: Python remainder(gx+1, 2) - 1 via floor-mod
        float xp = gx + 1.0f;
        gx = xp - 2.0f * floorf(xp * 0.5f) - 1.0f;

        float ix = (gx + 1.0f) * ((float)W_ * 0.5f) - 0.5f;
        float iy = (gy + 1.0f) * ((float)H_ * 0.5f) - 0.5f;

        float x0f = floorf(ix);
        float y0f = floorf(iy);
        float wx = ix - x0f;
        float wy = iy - y0f;

        int x0 = (int)x0f;
        int y0 = (int)y0f;
        int y1 = y0 + 1;

        // this lane's x tap
        int xs = x0 + sx;
        float wxs = sx ? wx : (1.0f - wx);
        float vx = (xs >= 0 && xs < W_) ? 1.0f : 0.0f;
        int cx = min(max(xs, 0), W_ - 1);

        // this lane's row within dup block b
        int b = min(max(y0, 0), H_ - 1);
        int row = b + r;
        float wys = (row == y0 && row < H_) ? (1.0f - wy)
                  : ((row == y1 && row < H_) ? wy : 0.0f);

        float wgt = wxs * vx * wys;

        // dup slot address: ((b*W + cx)*2 + r) * 16 bytes
        const uint4 p = *reinterpret_cast<const uint4*>(
            imgk + (((size_t)(b * W_ + cx) << 1) + r) * (C_ * sizeof(__half)));

        accum_tap(p, wgt, a0, a1, a2, a3, a4, a5, a6, a7);

        imgk += (size_t)HW_ * 2 * C_ * sizeof(__half);
    }

    // merge the quad: xor 1 (row pairs), xor 2 (x sides)
    a0 += __shfl_xor_sync(0xFFFFFFFFu, a0, 1);
    a1 += __shfl_xor_sync(0xFFFFFFFFu, a1, 1);
    a2 += __shfl_xor_sync(0xFFFFFFFFu, a2, 1);
    a3 += __shfl_xor_sync(0xFFFFFFFFu, a3, 1);
    a4 += __shfl_xor_sync(0xFFFFFFFFu, a4, 1);
    a5 += __shfl_xor_sync(0xFFFFFFFFu, a5, 1);
    a6 += __shfl_xor_sync(0xFFFFFFFFu, a6, 1);
    a7 += __shfl_xor_sync(0xFFFFFFFFu, a7, 1);

    a0 += __shfl_xor_sync(0xFFFFFFFFu, a0, 2);
    a1 += __shfl_xor_sync(0xFFFFFFFFu, a1, 2);
    a2 += __shfl_xor_sync(0xFFFFFFFFu, a2, 2);
    a3 += __shfl_xor_sync(0xFFFFFFFFu, a3, 2);
    a4 += __shfl_xor_sync(0xFFFFFFFFu, a4, 2);
    a5 += __shfl_xor_sync(0xFFFFFFFFu, a5, 2);
    a6 += __shfl_xor_sync(0xFFFFFFFFu, a6, 2);
    a7 += __shfl_xor_sync(0xFFFFFFFFu, a7, 2);

    if (s == 0) {
        float* o = out + (size_t)t * C_ * HW_ + hw;
        o[0 * HW_] = a0;
        o[1 * HW_] = a1;
        o[2 * HW_] = a2;
        o[3 * HW_] = a3;
        o[4 * HW_] = a4;
        o[5 * HW_] = a5;
        o[6 * HW_] = a6;
        o[7 * HW_] = a7;
    }
}

// ---------------------------------------------------------------------------
extern "C" void kernel_launch(void* const* d_in, const int* in_sizes, int n_in,
                              void* d_out, int out_size) {
    const float* flows  = (const float*)d_in[0];   // [1,16,2,128,128]
    const float* images = (const float*)d_in[1];   // [1,16,8,128,128]
    float* out = (float*)d_out;                    // [1,16,8,128,128]

    (void)in_sizes; (void)n_in; (void)out_size;

    {
        int total = L_ * HW_;
        build_dup_kernel<<<(total + 255) / 256, 256>>>(images);
    }
    {
        cumsum_flows_kernel<<<(HW_ + 255) / 256, 256>>>(flows);
    }
    {
        dim3 grid(H_, L_);
        dim3 block(512);
        pscan_sample_kernel<<<grid, block>>>(out);
    }
}